// round 16
// baseline (speedup 1.0000x reference)
#include <cuda_runtime.h>
#include <cuda_fp16.h>
#include <cstdint>

// Problem constants
#define BB 8
#define NN 2048
#define HH 4
#define DD 64
#define OUTC 256

// log2(e) / sqrt(D)
#define SCALE_LOG2E (1.4426950408889634f * 0.125f)

// Scratch (device globals; no cudaMalloc allowed)
__device__ __half g_qh [BB * HH * NN * DD];   // prescaled Q fp16, [bh][n][d]
__device__ __half g_kh [BB * HH * NN * DD];   // K fp16, [bh][n][d]
__device__ __half g_vh [BB * HH * NN * DD];   // V fp16, [bh][n][d]
__device__ __half g_oh [BB * NN * HH * DD];   // O fp16, [b*n][h*d]
__device__ __half g_wpth[OUTC * HH * DD];     // Wp^T fp16, [out][k]

// ==================== helpers ====================
__device__ __forceinline__ uint32_t smem_u32(const void* p) {
    uint32_t a;
    asm("{ .reg .u64 t; cvta.to.shared.u64 t, %1; cvt.u32.u64 %0, t; }" : "=r"(a) : "l"(p));
    return a;
}
__device__ __forceinline__ void cp16(uint32_t dst, const void* src) {
    asm volatile("cp.async.cg.shared.global [%0], [%1], 16;" :: "r"(dst), "l"(src) : "memory");
}
#define CP_COMMIT asm volatile("cp.async.commit_group;" ::: "memory")
#define CP_WAIT(n) asm volatile("cp.async.wait_group %0;" :: "n"(n) : "memory")

#define LDSM4(r, a) \
    asm volatile("ldmatrix.sync.aligned.m8n8.x4.shared.b16 {%0,%1,%2,%3}, [%4];" \
        : "=r"((r)[0]), "=r"((r)[1]), "=r"((r)[2]), "=r"((r)[3]) : "r"(a))
#define LDSM4T(r, a) \
    asm volatile("ldmatrix.sync.aligned.m8n8.x4.trans.shared.b16 {%0,%1,%2,%3}, [%4];" \
        : "=r"((r)[0]), "=r"((r)[1]), "=r"((r)[2]), "=r"((r)[3]) : "r"(a))
#define LDSM2T(r0, r1, a) \
    asm volatile("ldmatrix.sync.aligned.m8n8.x2.trans.shared.b16 {%0,%1}, [%2];" \
        : "=r"(r0), "=r"(r1) : "r"(a))

__device__ __forceinline__ void hmma(float* c, const uint32_t* a, uint32_t b0, uint32_t b1) {
    asm volatile(
        "mma.sync.aligned.m16n8k16.row.col.f32.f16.f16.f32 "
        "{%0,%1,%2,%3}, {%4,%5,%6,%7}, {%8,%9}, {%0,%1,%2,%3};"
        : "+f"(c[0]), "+f"(c[1]), "+f"(c[2]), "+f"(c[3])
        : "r"(a[0]), "r"(a[1]), "r"(a[2]), "r"(a[3]), "r"(b0), "r"(b1));
}
__device__ __forceinline__ uint32_t pack_h2(float x, float y) {
    __half2 h = __floats2half2_rn(x, y);
    return *(uint32_t*)&h;
}
// exp2 of a packed half2 on the MUFU pipe
__device__ __forceinline__ uint32_t hex2(uint32_t x) {
    uint32_t y;
    asm("ex2.approx.f16x2 %0, %1;" : "=r"(y) : "r"(x));
    return y;
}

// ==================== Kernel 1: QKV projection (persistent, pipelined, single-pass fp16) ====================
// grid (8, 32) = 256 CTAs, 128 threads (4 warps), 2 CTAs/SM. Each CTA: W staged once,
// then 4 tiles of 64 rows, double-buffered fp32 X via cp.async -> convert -> MMA.
// Smem: W[w] @ w*9216 (27648), Xf32 dbuf @27648 (2*16384), Xh dbuf @60416 (2*9216). Total 78848.
#define QKV_W    0
#define QKV_XF   27648
#define QKV_XH   60416
#define QKV_SMEM 78848

__global__ __launch_bounds__(128, 2) void qkv_kernel(
    const float* __restrict__ x,
    const float* __restrict__ Wq, const float* __restrict__ Wk, const float* __restrict__ Wv,
    const float* __restrict__ bq, const float* __restrict__ bk, const float* __restrict__ bv,
    const float* __restrict__ Wp)
{
    extern __shared__ char smc[];
    const uint32_t sb = smem_u32(smc);
    const int tid  = threadIdx.x;
    const int warp = tid >> 5, lane = tid & 31;
    const int gid  = lane >> 2, tq = lane & 3;
    const int bh = blockIdx.y;
    const int b  = bh >> 2, h = bh & 3;
    const int r0 = blockIdx.x * 256;

    // folded Wp transpose: 256 CTAs x 1 row of Wp^T each (128 threads -> 2 elems)
    {
        int bid = blockIdx.y * 8 + blockIdx.x;   // 0..255
        g_wpth[bid * 256 + tid]       = __float2half_rn(Wp[tid * 256 + bid]);
        g_wpth[bid * 256 + tid + 128] = __float2half_rn(Wp[(tid + 128) * 256 + bid]);
    }

    // prefetch fp32 X tile 0 via cp.async (64 rows x 16 float4)
    for (int i = tid; i < 1024; i += 128) {
        int r = i >> 4, c4 = i & 15;
        cp16(sb + QKV_XF + r * 256 + c4 * 16,
             x + (size_t)(b * NN + r0 + r) * 256 + h * 64 + c4 * 4);
    }
    CP_COMMIT;

    // stage ALL three W^T (fp16) once
    #pragma unroll
    for (int w = 0; w < 3; ++w) {
        const float* Wsrc = (w == 0) ? Wq : (w == 1) ? Wk : Wv;
        char* wbase = smc + QKV_W + w * 9216;
        for (int i = tid; i < 4096; i += 128) {
            int d = i >> 6, e = i & 63;
            *(__half*)(wbase + (e * 72 + d) * 2) = __float2half_rn(Wsrc[h * 4096 + i]);
        }
    }

    const uint32_t aoff = (uint32_t)((lane & 15) * 144 + ((lane & 16) ? 16 : 0));
    const uint32_t boff = (uint32_t)(((lane & 7) + ((lane & 16) ? 8 : 0)) * 144 + ((lane & 8) ? 16 : 0));

    for (int t = 0; t < 4; ++t) {
        const int rt0 = r0 + t * 64;
        // prefetch next fp32 tile
        if (t + 1 < 4) {
            for (int i = tid; i < 1024; i += 128) {
                int r = i >> 4, c4 = i & 15;
                cp16(sb + QKV_XF + ((t + 1) & 1) * 16384 + r * 256 + c4 * 16,
                     x + (size_t)(b * NN + rt0 + 64 + r) * 256 + h * 64 + c4 * 4);
            }
            CP_COMMIT;
            CP_WAIT(1);
        } else {
            CP_WAIT(0);
        }
        __syncthreads();

        // convert fp32 tile -> fp16 (padded rows 144 B)
        {
            const char* xf = smc + QKV_XF + (t & 1) * 16384;
            char* xh = smc + QKV_XH + (t & 1) * 9216;
            for (int i = tid; i < 1024; i += 128) {
                int r = i >> 4, c4 = i & 15;
                float4 v = *(const float4*)(xf + r * 256 + c4 * 16);
                __half2 h0 = __floats2half2_rn(v.x, v.y);
                __half2 h1 = __floats2half2_rn(v.z, v.w);
                *(uint2*)(xh + r * 144 + c4 * 8) =
                    make_uint2(*(uint32_t*)&h0, *(uint32_t*)&h1);
            }
        }
        __syncthreads();

        const uint32_t xb = sb + QKV_XH + (t & 1) * 9216;
        const int row0 = rt0 + warp * 16 + gid;

        #pragma unroll
        for (int w = 0; w < 3; ++w) {
            const float* bias = (w == 0) ? bq : (w == 1) ? bk : bv;
            __half* dst = (w == 0) ? g_qh : (w == 1) ? g_kh : g_vh;
            const uint32_t wb = sb + QKV_W + w * 9216;

            float acc[8][4];
            #pragma unroll
            for (int i = 0; i < 8; i++)
                #pragma unroll
                for (int j = 0; j < 4; j++) acc[i][j] = 0.0f;

            #pragma unroll
            for (int kk = 0; kk < 4; kk++) {
                uint32_t ah[4];
                LDSM4(ah, xb + warp * 16 * 144 + kk * 32 + aoff);
                #pragma unroll
                for (int p = 0; p < 4; p++) {
                    uint32_t bh4[4];
                    LDSM4(bh4, wb + p * 16 * 144 + kk * 32 + boff);
                    hmma(acc[2 * p],     ah, bh4[0], bh4[1]);
                    hmma(acc[2 * p + 1], ah, bh4[2], bh4[3]);
                }
            }

            const float qscale = (w == 0) ? SCALE_LOG2E : 1.0f;
            size_t rb0 = ((size_t)bh * NN + row0) * 64;
            size_t rb1 = rb0 + 8 * 64;
            #pragma unroll
            for (int nd = 0; nd < 8; nd++) {
                int c = nd * 8 + tq * 2;
                float b0 = bias[h * 64 + c], b1 = bias[h * 64 + c + 1];
                *(uint32_t*)&dst[rb0 + c] =
                    pack_h2((acc[nd][0] + b0) * qscale, (acc[nd][1] + b1) * qscale);
                *(uint32_t*)&dst[rb1 + c] =
                    pack_h2((acc[nd][2] + b0) * qscale, (acc[nd][3] + b1) * qscale);
            }
        }
        __syncthreads();   // done reading fp16 buffer before it is rewritten
    }
}

// ==================== Kernel 2: HMMA fp16 flash attention ====================
// grid (16, 32), 128 threads = 4 warps; warp w owns rows w*32..w*32+31, all keys.
// 3 CTAs/SM. Per-16-key-block interleaved S->exp->PV; rowsums via ones-column.
#define TILE_B   9216
#define BUF_B    18432
#define ATTN_SMEM (2 * BUF_B)

__device__ __forceinline__ void stage_tiles(uint32_t base, int kc0, int tid,
    const __half* kh, const __half* vh)
{
    for (int i = tid; i < 512; i += 128) {
        int r = i >> 3, c = i & 7;
        uint32_t d0 = base + r * 144 + c * 16;
        cp16(d0,          kh + (size_t)(kc0 + r) * 64 + c * 8);
        cp16(d0 + TILE_B, vh + (size_t)(kc0 + r) * 64 + c * 8);
    }
}

__global__ __launch_bounds__(128, 3) void attn_kernel()
{
    extern __shared__ char smc[];
    const uint32_t sb = smem_u32(smc);
    const int tid  = threadIdx.x;
    const int warp = tid >> 5, lane = tid & 31;
    const int gid  = lane >> 2, tq = lane & 3;
    const int bh = blockIdx.y;
    const int b  = bh >> 2, h = bh & 3;
    const int q0 = blockIdx.x * 128;

    const __half* qh = g_qh + (size_t)bh * NN * 64;
    const __half* kh = g_kh + (size_t)bh * NN * 64;
    const __half* vh = g_vh + (size_t)bh * NN * 64;

    stage_tiles(sb, 0, tid, kh, vh);
    CP_COMMIT;

    // ones-column init: V padding halves 64..71 <- {1.0, 0...}, both buffers
    {
        int buf = tid >> 6, r = tid & 63;
        uint4 v = make_uint4(0x00003C00u, 0u, 0u, 0u);
        *(uint4*)(smc + buf * BUF_B + TILE_B + r * 144 + 128) = v;
    }

    // Q a-frags: 2 m16 tiles (rows warp*32 + mi*16 + {gid, gid+8})
    const int rbase = q0 + warp * 32 + gid;
    uint32_t qa[4][2][4];
    #pragma unroll
    for (int kk = 0; kk < 4; kk++)
        #pragma unroll
        for (int mi = 0; mi < 2; mi++) {
            const __half* qrow = qh + (size_t)(rbase + mi * 16) * 64 + kk * 16 + tq * 2;
            qa[kk][mi][0] = *(const uint32_t*)(qrow);
            qa[kk][mi][1] = *(const uint32_t*)(qrow + 8 * 64);
            qa[kk][mi][2] = *(const uint32_t*)(qrow + 8);
            qa[kk][mi][3] = *(const uint32_t*)(qrow + 8 * 64 + 8);
        }

    float oacc[2][8][4];
    #pragma unroll
    for (int mi = 0; mi < 2; mi++)
        #pragma unroll
        for (int i = 0; i < 8; i++)
            #pragma unroll
            for (int j = 0; j < 4; j++) oacc[mi][i][j] = 0.0f;
    float rsacc[2][4];
    #pragma unroll
    for (int mi = 0; mi < 2; mi++)
        #pragma unroll
        for (int j = 0; j < 4; j++) rsacc[mi][j] = 0.0f;

    const uint32_t koff =
        (uint32_t)(((lane & 7) + ((lane & 16) ? 8 : 0)) * 144 + ((lane & 8) ? 16 : 0));
    const uint32_t voff =
        (uint32_t)((lane & 15) * 144 + ((lane & 16) ? 16 : 0));
    const uint32_t ooff = (uint32_t)((lane & 15) * 144 + 128);   // ones column

    for (int kt = 0; kt < NN / 64; ++kt) {
        __syncthreads();
        if (kt + 1 < NN / 64) {
            stage_tiles(sb + ((kt + 1) & 1) * BUF_B, (kt + 1) * 64, tid, kh, vh);
            CP_COMMIT;
            CP_WAIT(1);
        } else {
            CP_WAIT(0);
        }
        __syncthreads();
        const uint32_t kbase = sb + (kt & 1) * BUF_B;

        // ---- per 16-key block: S -> exp (f16x2 MUFU) -> PV + rowsum ----
        #pragma unroll
        for (int p = 0; p < 4; p++) {
            float sacc[2][2][4];
            #pragma unroll
            for (int mi = 0; mi < 2; mi++)
                #pragma unroll
                for (int i = 0; i < 2; i++)
                    #pragma unroll
                    for (int j = 0; j < 4; j++) sacc[mi][i][j] = 0.0f;

            #pragma unroll
            for (int kk = 0; kk < 4; kk++) {
                uint32_t bb[4];
                LDSM4(bb, kbase + p * 16 * 144 + kk * 32 + koff);
                #pragma unroll
                for (int mi = 0; mi < 2; mi++) {
                    hmma(sacc[mi][0], qa[kk][mi], bb[0], bb[1]);
                    hmma(sacc[mi][1], qa[kk][mi], bb[2], bb[3]);
                }
            }

            // exp: pack S to half2, ex2.approx.f16x2 -> P a-frags (m16k16)
            uint32_t pa[2][4];
            #pragma unroll
            for (int mi = 0; mi < 2; mi++) {
                pa[mi][0] = hex2(pack_h2(sacc[mi][0][0], sacc[mi][0][1]));
                pa[mi][1] = hex2(pack_h2(sacc[mi][0][2], sacc[mi][0][3]));
                pa[mi][2] = hex2(pack_h2(sacc[mi][1][0], sacc[mi][1][1]));
                pa[mi][3] = hex2(pack_h2(sacc[mi][1][2], sacc[mi][1][3]));
            }

            // PV over this block's 16 keys
            #pragma unroll
            for (int ndp = 0; ndp < 4; ndp++) {
                uint32_t bb[4];
                LDSM4T(bb, kbase + TILE_B + p * 16 * 144 + ndp * 32 + voff);
                #pragma unroll
                for (int mi = 0; mi < 2; mi++) {
                    hmma(oacc[mi][2 * ndp],     pa[mi], bb[0], bb[1]);
                    hmma(oacc[mi][2 * ndp + 1], pa[mi], bb[2], bb[3]);
                }
            }
            // rowsum via ones column (exact fp32 sum of fp16 P)
            {
                uint32_t o0, o1;
                LDSM2T(o0, o1, kbase + TILE_B + p * 16 * 144 + ooff);
                hmma(rsacc[0], pa[0], o0, o1);
                hmma(rsacc[1], pa[1], o0, o1);
            }
        }
    }

    // ---- normalize and write O fp16 (rowsum in col 0 -> tq==0 lanes) ----
    #pragma unroll
    for (int mi = 0; mi < 2; mi++) {
        float rsum0 = __shfl_sync(0xffffffffu, rsacc[mi][0], lane & 28);
        float rsum1 = __shfl_sync(0xffffffffu, rsacc[mi][2], lane & 28);
        const float inv0 = 1.0f / rsum0;
        const float inv1 = 1.0f / rsum1;
        size_t ob0 = ((size_t)(b * NN + rbase + mi * 16)) * 256 + h * 64;
        size_t ob1 = ob0 + (size_t)8 * 256;
        #pragma unroll
        for (int nd = 0; nd < 8; nd++) {
            int c = nd * 8 + tq * 2;
            *(uint32_t*)&g_oh[ob0 + c] =
                pack_h2(oacc[mi][nd][0] * inv0, oacc[mi][nd][1] * inv0);
            *(uint32_t*)&g_oh[ob1 + c] =
                pack_h2(oacc[mi][nd][2] * inv1, oacc[mi][nd][3] * inv1);
        }
    }
}

// ==================== Kernel 3: output projection (HMMA fp16 single-pass, double-buffered) ====================
// grid (128, 4), 256 threads. Per-stage (27648 B): A @0 [128][72], W @18432 [64][72].
#define PST 27648
#define PROJ_SMEM (2 * PST)

__device__ __forceinline__ void stage_proj(char* smcb, int r0, int c0, int kb, int tid)
{
    uint32_t base = smem_u32(smcb);
    for (int i = tid; i < 1024; i += 256) {
        int r = i >> 3, c = i & 7;
        cp16(base + r * 144 + c * 16,
             g_oh + ((size_t)(r0 + r)) * 256 + kb * 64 + c * 8);
    }
    for (int i = tid; i < 512; i += 256) {
        int r = i >> 3, c = i & 7;
        cp16(base + 18432 + r * 144 + c * 16,
             g_wpth + ((size_t)(c0 + r)) * 256 + kb * 64 + c * 8);
    }
}

__global__ __launch_bounds__(256) void proj_kernel(
    const float* __restrict__ bp, float* __restrict__ out)
{
    extern __shared__ char smc[];
    const uint32_t sb = smem_u32(smc);
    const int tid  = threadIdx.x;
    const int warp = tid >> 5, lane = tid & 31;
    const int gid  = lane >> 2, tq = lane & 3;
    const int r0 = blockIdx.x * 128;
    const int c0 = blockIdx.y * 64;

    float acc[8][4];
    #pragma unroll
    for (int i = 0; i < 8; i++)
        #pragma unroll
        for (int j = 0; j < 4; j++) acc[i][j] = 0.0f;

    const uint32_t afoff =
        (uint32_t)((lane & 15) * 144 + ((lane & 16) ? 16 : 0));
    const uint32_t bfoff =
        (uint32_t)(((lane & 7) + ((lane & 16) ? 8 : 0)) * 144 + ((lane & 8) ? 16 : 0));

    stage_proj(smc, r0, c0, 0, tid);
    CP_COMMIT;

    for (int kb = 0; kb < 4; kb++) {
        if (kb + 1 < 4) {
            stage_proj(smc + ((kb + 1) & 1) * PST, r0, c0, kb + 1, tid);
            CP_COMMIT;
            CP_WAIT(1);
        } else {
            CP_WAIT(0);
        }
        __syncthreads();
        const uint32_t kbase = sb + (kb & 1) * PST;

        #pragma unroll
        for (int kk = 0; kk < 4; kk++) {
            uint32_t ah[4];
            LDSM4(ah, kbase + warp * 16 * 144 + kk * 32 + afoff);
            #pragma unroll
            for (int p = 0; p < 4; p++) {
                uint32_t bh4[4];
                LDSM4(bh4, kbase + 18432 + p * 16 * 144 + kk * 32 + bfoff);
                hmma(acc[2 * p],     ah, bh4[0], bh4[1]);
                hmma(acc[2 * p + 1], ah, bh4[2], bh4[3]);
            }
        }
        __syncthreads();   // done reading buffer (kb&1) before it is restaged
    }

    const int m0 = r0 + warp * 16 + gid;
    #pragma unroll
    for (int nd = 0; nd < 8; nd++) {
        int cc = c0 + nd * 8 + tq * 2;
        float b0 = bp[cc], b1 = bp[cc + 1];
        *(float2*)&out[(size_t)m0 * 256 + cc] =
            make_float2(acc[nd][0] + b0, acc[nd][1] + b1);
        *(float2*)&out[(size_t)(m0 + 8) * 256 + cc] =
            make_float2(acc[nd][2] + b0, acc[nd][3] + b1);
    }
}

// ==================== launch ====================
extern "C" void kernel_launch(void* const* d_in, const int* in_sizes, int n_in,
                              void* d_out, int out_size)
{
    (void)in_sizes; (void)n_in; (void)out_size;
    const float* x  = (const float*)d_in[0];
    const float* Wq = (const float*)d_in[1];
    const float* Wk = (const float*)d_in[2];
    const float* Wv = (const float*)d_in[3];
    const float* bq = (const float*)d_in[4];
    const float* bk = (const float*)d_in[5];
    const float* bv = (const float*)d_in[6];
    const float* Wp = (const float*)d_in[7];
    const float* bp = (const float*)d_in[8];
    float* out = (float*)d_out;

    cudaFuncSetAttribute(qkv_kernel,  cudaFuncAttributeMaxDynamicSharedMemorySize, QKV_SMEM);
    cudaFuncSetAttribute(attn_kernel, cudaFuncAttributeMaxDynamicSharedMemorySize, ATTN_SMEM);
    cudaFuncSetAttribute(proj_kernel, cudaFuncAttributeMaxDynamicSharedMemorySize, PROJ_SMEM);

    qkv_kernel<<<dim3(8, BB * HH), 128, QKV_SMEM>>>(x, Wq, Wk, Wv, bq, bk, bv, Wp);
    attn_kernel<<<dim3(NN / 128, BB * HH), 128, ATTN_SMEM>>>();
    proj_kernel<<<dim3((BB * NN) / 128, OUTC / 64), 256, PROJ_SMEM>>>(bp, out);
}